// round 16
// baseline (speedup 1.0000x reference)
#include <cuda_runtime.h>
#include <cuda_fp16.h>
#include <cstdint>

#define B_   64
#define L_   1024
#define KDIM 1024
#define HDIM 1024

// ---------------- device scratch (static globals: allocation-free rule) ----
__device__ float g_q[B_ * HDIM];                         // q = query @ W1^T
__device__ float g_spart[8 * B_ * L_];                   // per-N-slab partial scores
__device__ float g_ctxpart[8 * B_ * KDIM];               // context L-chunk partials
__device__ __align__(16) __half g_w2h[HDIM * KDIM];      // W2 fp16
__device__ __align__(16) __half g_keysh[B_ * L_ * KDIM]; // keys fp16 (128MB)

// ---------------- helpers ----------------
__device__ __forceinline__ uint32_t smem_to_u32(const void* p) {
    uint32_t a;
    asm("{ .reg .u64 t; cvta.to.shared.u64 t, %1; cvt.u32.u64 %0, t; }" : "=r"(a) : "l"(p));
    return a;
}
__device__ __forceinline__ void cp_async16(uint32_t dst, const void* src) {
    asm volatile("cp.async.cg.shared.global [%0], [%1], 16;" :: "r"(dst), "l"(src) : "memory");
}

#define MBARRIER_INIT(mbar, count) \
    asm volatile("mbarrier.init.shared.b64 [%0], %1;" :: "r"((uint32_t)(mbar)), "r"((uint32_t)(count)) : "memory")
#define CP_MBAR_ARRIVE(mbar) \
    asm volatile("cp.async.mbarrier.arrive.noinc.shared.b64 [%0];" :: "r"((uint32_t)(mbar)) : "memory")
#define MBAR_ARRIVE(mbar) \
    asm volatile("mbarrier.arrive.shared.b64 _, [%0];" :: "r"((uint32_t)(mbar)) : "memory")
#define MBARRIER_WAIT_PARITY(mbar, parity) do { \
    uint32_t _m = (uint32_t)(mbar); uint32_t _p = (uint32_t)(parity); uint32_t _d; \
    asm volatile("{\n\t.reg .pred p;\n\tmbarrier.try_wait.parity.acquire.cta.shared::cta.b64 p, [%1], %2;\n\tselp.b32 %0,1,0,p;\n\t}" \
                 : "=r"(_d) : "r"(_m), "r"(_p) : "memory"); \
    if (!_d) { \
        asm volatile("{\n\t.reg .pred P1;\n\tWL_%=:\n\tmbarrier.try_wait.parity.acquire.cta.shared::cta.b64 P1, [%0], %1, 0x989680;\n\t@P1 bra.uni WD_%=;\n\tbra.uni WL_%=;\n\tWD_%=:\n\t}" \
                     :: "r"(_m), "r"(_p) : "memory"); \
    } } while (0)

#define LDSM4(r, addr) \
    asm volatile("ldmatrix.sync.aligned.m8n8.x4.shared.b16 {%0,%1,%2,%3}, [%4];" \
                 : "=r"((r)[0]), "=r"((r)[1]), "=r"((r)[2]), "=r"((r)[3]) : "r"(addr))

#define MMA16816(d, a, b0, b1) \
    asm volatile("mma.sync.aligned.m16n8k16.row.col.f32.f16.f16.f32 " \
                 "{%0,%1,%2,%3}, {%4,%5,%6,%7}, {%8,%9}, {%0,%1,%2,%3};" \
                 : "+f"((d)[0]), "+f"((d)[1]), "+f"((d)[2]), "+f"((d)[3]) \
                 : "r"((a)[0]), "r"((a)[1]), "r"((a)[2]), "r"((a)[3]), "r"(b0), "r"(b1))

__device__ __forceinline__ float tanh_fast(float x) {
    float y;
    asm("tanh.approx.f32 %0, %1;" : "=f"(y) : "f"(x));
    return y;
}
__device__ __forceinline__ uint32_t cvt2(float x, float y) {
    __half2 h = __floats2half2_rn(x, y);
    return *(uint32_t*)&h;
}

// ---------------------------------------------------------------------------
// K0: fp32 -> fp16: keys (blocks [0,16384), MLP=4) and W2 (blocks [16384,17408))
// ---------------------------------------------------------------------------
__global__ __launch_bounds__(256) void convert_kernel(const float* __restrict__ keys,
                                                      const float* __restrict__ W2) {
    const int bx = blockIdx.x;
    if (bx < 16384) {
        const size_t base = (size_t)bx * 1024 + threadIdx.x;
        float4 f[4];
#pragma unroll
        for (int i = 0; i < 4; i++) f[i] = ((const float4*)keys)[base + i * 256];
#pragma unroll
        for (int i = 0; i < 4; i++)
            ((uint2*)g_keysh)[base + i * 256] =
                make_uint2(cvt2(f[i].x, f[i].y), cvt2(f[i].z, f[i].w));
    } else {
        int i4 = (bx - 16384) * 256 + threadIdx.x;
        float4 f = ((const float4*)W2)[i4];
        ((uint2*)g_w2h)[i4] = make_uint2(cvt2(f.x, f.y), cvt2(f.z, f.w));
    }
}

// ---------------------------------------------------------------------------
// K1: batch-tiled qproj — block computes 256 h-values x 8 batches.
// ---------------------------------------------------------------------------
__global__ __launch_bounds__(256) void qproj_kernel(const float* __restrict__ query,
                                                    const float* __restrict__ W1) {
    __shared__ float qs[8][KDIM];
    const int tid = threadIdx.x;
    const int b0 = blockIdx.y * 8;
    const int h = blockIdx.x * 256 + tid;
    for (int i = tid; i < 8 * KDIM / 4; i += 256) {
        int bb = i / (KDIM / 4), kk = (i % (KDIM / 4)) * 4;
        *(float4*)&qs[bb][kk] = *(const float4*)(query + (size_t)(b0 + bb) * KDIM + kk);
    }
    __syncthreads();
    const float* w = W1 + (size_t)h * KDIM;
    float acc[8];
#pragma unroll
    for (int bb = 0; bb < 8; bb++) acc[bb] = 0.f;
#pragma unroll 2
    for (int k = 0; k < KDIM; k += 4) {
        float4 w4 = *(const float4*)(w + k);
#pragma unroll
        for (int bb = 0; bb < 8; bb++) {
            acc[bb] = fmaf(qs[bb][k + 0], w4.x, acc[bb]);
            acc[bb] = fmaf(qs[bb][k + 1], w4.y, acc[bb]);
            acc[bb] = fmaf(qs[bb][k + 2], w4.z, acc[bb]);
            acc[bb] = fmaf(qs[bb][k + 3], w4.w, acc[bb]);
        }
    }
#pragma unroll
    for (int bb = 0; bb < 8; bb++)
        g_q[(b0 + bb) * HDIM + h] = acc[bb];
}

// ---------------------------------------------------------------------------
// K2: HMMA score kernel (128x128 tile, 256 thr, 2 CTA/SM).
// mbarrier producer/consumer pipeline. empty[s] now takes ONE arrive per warp
// (count 8) — LDSM/MMA are warp-synchronous so an elected-lane arrive after
// __syncwarp() is sufficient; 32x fewer mbarrier atomics per chunk.
// ---------------------------------------------------------------------------
#define BH_OFF   16384u
#define STAGE_SZ 32768u
#define MB_OFF   98304u
#define QS_OFF   98432u
#define VS_OFF   98944u
#define RED_OFF  99456u
#define SMEM_SCORE (99456 + 2048)

__device__ __forceinline__ void load_chunk(uint32_t st, int c, int R0, int h0,
                                           int lrow, int ltc) {
    const uint32_t swz = (uint32_t)((ltc ^ (lrow & 7)) << 4);
    const __half* gA = g_keysh + (size_t)R0 * KDIM + c * 64 + ltc * 8;
    const __half* gH = g_w2h + (size_t)h0 * KDIM + c * 64 + ltc * 8;
#pragma unroll
    for (int p = 0; p < 4; p++) {
        int r = lrow + (p << 5);
        uint32_t off = (uint32_t)(r << 7) + swz;
        size_t gi = (size_t)r * KDIM;
        cp_async16(st + off, gA + gi);
        cp_async16(st + BH_OFF + off, gH + gi);
    }
}

__global__ __launch_bounds__(256, 2) void score_kernel(const float* __restrict__ v) {
    extern __shared__ char smem[];
    const uint32_t sb = smem_to_u32(smem);
    const uint32_t mb = sb + MB_OFF;
    const int tid = threadIdx.x;
    const int lane = tid & 31, warp = tid >> 5;
    const int wm = warp & 1, wn = warp >> 1;
    const int bx = blockIdx.x;
    const int nq = bx & 7, bm = bx >> 3;
    const int R0 = bm << 7, b = bm >> 3, h0 = nq << 7;

    float* qsp = (float*)(smem + QS_OFF);
    float* vsp = (float*)(smem + VS_OFF);
    float* red = (float*)(smem + RED_OFF);

    if (tid == 0) {
#pragma unroll
        for (int s = 0; s < 3; s++) {
            MBARRIER_INIT(mb + s * 16, 256);      // full[s]: per-thread cp.async arrive
            MBARRIER_INIT(mb + s * 16 + 8, 8);    // empty[s]: one arrive per warp
        }
    }
    if (tid < 128) {
        qsp[tid] = g_q[b * HDIM + h0 + tid];
        vsp[tid] = v[h0 + tid];
    }
    __syncthreads();

    float acc[4][4][4];
#pragma unroll
    for (int i = 0; i < 4; i++)
#pragma unroll
        for (int j = 0; j < 4; j++)
#pragma unroll
            for (int e = 0; e < 4; e++) acc[i][j][e] = 0.f;

    const int lrow = tid >> 3, ltc = tid & 7;
    const int rbank = lane & 7;
    const int a_sub = (((lane >> 3) & 1) << 3) + rbank;
    const int a_gl  = lane >> 4;
    const int b_sub = (((lane >> 4) & 1) << 3) + rbank;
    const int b_gl  = (lane >> 3) & 1;

    // prologue: fill stages 0,1 (chunks 0,1)
    load_chunk(sb, 0, R0, h0, lrow, ltc);
    CP_MBAR_ARRIVE(mb + 0);
    load_chunk(sb + STAGE_SZ, 1, R0, h0, lrow, ltc);
    CP_MBAR_ARRIVE(mb + 16);

#pragma unroll 1
    for (int c = 0; c < 16; c++) {
        const int c2 = c + 2;
        if (c2 < 16) {
            const int s2 = c2 % 3;
            if (c2 >= 3)
                MBARRIER_WAIT_PARITY(mb + s2 * 16 + 8, ((c2 / 3) - 1) & 1);
            load_chunk(sb + (uint32_t)s2 * STAGE_SZ, c2, R0, h0, lrow, ltc);
            CP_MBAR_ARRIVE(mb + s2 * 16);
        }
        const int s = c % 3;
        MBARRIER_WAIT_PARITY(mb + s * 16, (c / 3) & 1);
        const uint32_t stA = sb + (uint32_t)s * STAGE_SZ;

#pragma unroll
        for (int ks = 0; ks < 4; ks++) {
            uint32_t a[4][4], bh[2][4];
#pragma unroll
            for (int mi = 0; mi < 4; mi++) {
                int row = (wm << 6) + (mi << 4) + a_sub;
                int g = (ks << 1) + a_gl;
                LDSM4(a[mi], stA + (uint32_t)(row << 7) + (uint32_t)((g ^ rbank) << 4));
            }
#pragma unroll
            for (int nd = 0; nd < 2; nd++) {
                int row = (wn << 5) + (nd << 4) + b_sub;
                int g = (ks << 1) + b_gl;
                LDSM4(bh[nd], stA + BH_OFF + (uint32_t)(row << 7) + (uint32_t)((g ^ rbank) << 4));
            }
#pragma unroll
            for (int mi = 0; mi < 4; mi++)
#pragma unroll
                for (int ni = 0; ni < 4; ni++)
                    MMA16816(acc[mi][ni], a[mi], bh[ni >> 1][(ni & 1) * 2], bh[ni >> 1][(ni & 1) * 2 + 1]);
        }
        __syncwarp();
        if (lane == 0) MBAR_ARRIVE(mb + s * 16 + 8);   // warp done reading stage s
    }
    __syncthreads();

    // ---- fused epilogue: v-weighted tanh row sums ----
    const int rq = lane >> 2, j0 = (lane & 3) * 2;
    float rsum[4][2];
#pragma unroll
    for (int mi = 0; mi < 4; mi++) { rsum[mi][0] = 0.f; rsum[mi][1] = 0.f; }
#pragma unroll
    for (int mi = 0; mi < 4; mi++)
#pragma unroll
        for (int ni = 0; ni < 4; ni++) {
            int nb = (wn << 5) + (ni << 3) + j0;
            float q0 = qsp[nb], q1 = qsp[nb + 1];
            float v0 = vsp[nb], v1 = vsp[nb + 1];
            rsum[mi][0] = fmaf(v0, tanh_fast(q0 + acc[mi][ni][0]),
                          fmaf(v1, tanh_fast(q1 + acc[mi][ni][1]), rsum[mi][0]));
            rsum[mi][1] = fmaf(v0, tanh_fast(q0 + acc[mi][ni][2]),
                          fmaf(v1, tanh_fast(q1 + acc[mi][ni][3]), rsum[mi][1]));
        }
#pragma unroll
    for (int mi = 0; mi < 4; mi++)
#pragma unroll
        for (int h = 0; h < 2; h++) {
            float s = rsum[mi][h];
            s += __shfl_xor_sync(0xffffffffu, s, 1);
            s += __shfl_xor_sync(0xffffffffu, s, 2);
            if ((lane & 3) == 0)
                red[wn * 128 + (wm << 6) + (mi << 4) + (h << 3) + rq] = s;
        }
    __syncthreads();
    if (tid < 128) {
        float s = red[tid] + red[128 + tid] + red[256 + tid] + red[384 + tid];
        g_spart[nq * (B_ * L_) + R0 + tid] = s;
    }
}

// ---------------------------------------------------------------------------
// K3: masked softmax (sums the 8 N-slab partials). mask is int32.
// ---------------------------------------------------------------------------
__global__ __launch_bounds__(256) void softmax_kernel(const int* __restrict__ mask,
                                                      float* __restrict__ wout) {
    const int b = blockIdx.x;
    const int tid = threadIdx.x;
    const float NINF = __int_as_float(0xff800000);
    __shared__ float sred[8];
    __shared__ float sbcast;

    float vals[4];
    float mx = NINF;
#pragma unroll
    for (int i = 0; i < 4; i++) {
        int idx = b * L_ + tid + i * 256;
        float s = 0.f;
#pragma unroll
        for (int p = 0; p < 8; p++) s += g_spart[p * (B_ * L_) + idx];
        if (mask[idx] != 0) s = NINF;
        vals[i] = s;
        mx = fmaxf(mx, s);
    }
#pragma unroll
    for (int off = 16; off > 0; off >>= 1)
        mx = fmaxf(mx, __shfl_xor_sync(0xffffffffu, mx, off));
    if ((tid & 31) == 0) sred[tid >> 5] = mx;
    __syncthreads();
    if (tid == 0) {
        float m = sred[0];
#pragma unroll
        for (int w = 1; w < 8; w++) m = fmaxf(m, sred[w]);
        sbcast = m;
    }
    __syncthreads();
    mx = sbcast;
    __syncthreads();

    float e[4];
    float sum = 0.f;
    if (mx == NINF) {
#pragma unroll
        for (int i = 0; i < 4; i++) e[i] = 0.f;
        sum = 1.f;
    } else {
#pragma unroll
        for (int i = 0; i < 4; i++) { e[i] = __expf(vals[i] - mx); sum += e[i]; }
    }
#pragma unroll
    for (int off = 16; off > 0; off >>= 1)
        sum += __shfl_xor_sync(0xffffffffu, sum, off);
    if ((tid & 31) == 0) sred[tid >> 5] = sum;
    __syncthreads();
    if (tid == 0) {
        float s = 0.f;
#pragma unroll
        for (int w = 0; w < 8; w++) s += sred[w];
        sbcast = (mx == NINF) ? 1.f : s;
    }
    __syncthreads();
    float inv = __fdividef(1.f, sbcast);
#pragma unroll
    for (int i = 0; i < 4; i++)
        wout[b * L_ + tid + i * 256] = e[i] * inv;
}

// ---------------------------------------------------------------------------
// K4a: context partials over 8 L-chunks of 128, reading fp16 keys
// ---------------------------------------------------------------------------
__global__ __launch_bounds__(256) void context_part_kernel(const float* __restrict__ wts) {
    const int b = blockIdx.y;
    const int chunk = blockIdx.z;
    const int col2 = blockIdx.x * 256 + threadIdx.x;
    __shared__ float ws[128];
    if (threadIdx.x < 128) ws[threadIdx.x] = wts[b * L_ + chunk * 128 + threadIdx.x];
    __syncthreads();
    const __half2* kp = (const __half2*)g_keysh + ((size_t)b * L_ + chunk * 128) * 512 + col2;
    float a0 = 0.f, a1 = 0.f;
#pragma unroll 8
    for (int l = 0; l < 128; l++) {
        float2 f = __half22float2(kp[(size_t)l * 512]);
        float w = ws[l];
        a0 = fmaf(w, f.x, a0);
        a1 = fmaf(w, f.y, a1);
    }
    float* dst = g_ctxpart + ((size_t)chunk * B_ + b) * KDIM + col2 * 2;
    *(float2*)dst = make_float2(a0, a1);
}

// ---------------------------------------------------------------------------
// K4b: sum the 8 context partials (deterministic)
// ---------------------------------------------------------------------------
__global__ __launch_bounds__(256) void context_reduce_kernel(float* __restrict__ ctx) {
    const int i = blockIdx.x * 256 + threadIdx.x;
    const int BK = B_ * KDIM;
    float s = 0.f;
#pragma unroll
    for (int p = 0; p < 8; p++) s += g_ctxpart[p * BK + i];
    ctx[i] = s;
}

// ---------------------------------------------------------------------------
extern "C" void kernel_launch(void* const* d_in, const int* in_sizes, int n_in,
                              void* d_out, int out_size) {
    const float* query = (const float*)d_in[0];   // [B, Q]
    const float* keys  = (const float*)d_in[1];   // [B, L, K]
    const int*   mask  = (const int*)d_in[2];     // [B, L] bool -> int32
    const float* W1    = (const float*)d_in[3];   // [H, Q]
    const float* W2    = (const float*)d_in[4];   // [H, K]
    const float* v     = (const float*)d_in[5];   // [1, H]

    float* out = (float*)d_out;
    float* ctx = out;                 // [B, K]
    float* wts = out + B_ * KDIM;     // [B, L]

    cudaFuncSetAttribute(score_kernel, cudaFuncAttributeMaxDynamicSharedMemorySize,
                         SMEM_SCORE);

    convert_kernel<<<17408, 256>>>(keys, W2);
    qproj_kernel<<<dim3(HDIM / 256, B_ / 8), 256>>>(query, W1);
    score_kernel<<<4096, 256, SMEM_SCORE>>>(v);
    softmax_kernel<<<B_, 256>>>(mask, wts);
    context_part_kernel<<<dim3(2, B_, 8), 256>>>(wts);
    context_reduce_kernel<<<B_ * KDIM / 256, 256>>>(ctx);
}

// round 17
// speedup vs baseline: 1.0197x; 1.0197x over previous
#include <cuda_runtime.h>
#include <cuda_fp16.h>
#include <cstdint>

#define B_   64
#define L_   1024
#define KDIM 1024
#define HDIM 1024

// ---------------- device scratch (static globals: allocation-free rule) ----
__device__ float g_q[B_ * HDIM];                         // q = query @ W1^T
__device__ float g_spart[8 * B_ * L_];                   // per-N-slab partial scores
__device__ float g_ctxpart[8 * B_ * KDIM];               // context L-chunk partials
__device__ __align__(16) __half g_w2h[HDIM * KDIM];      // W2 fp16
__device__ __align__(16) __half g_keysh[B_ * L_ * KDIM]; // keys fp16 (128MB)

// ---------------- helpers ----------------
__device__ __forceinline__ uint32_t smem_to_u32(const void* p) {
    uint32_t a;
    asm("{ .reg .u64 t; cvta.to.shared.u64 t, %1; cvt.u32.u64 %0, t; }" : "=r"(a) : "l"(p));
    return a;
}
__device__ __forceinline__ void cp_async16(uint32_t dst, const void* src) {
    asm volatile("cp.async.cg.shared.global [%0], [%1], 16;" :: "r"(dst), "l"(src) : "memory");
}

#define MBARRIER_INIT(mbar, count) \
    asm volatile("mbarrier.init.shared.b64 [%0], %1;" :: "r"((uint32_t)(mbar)), "r"((uint32_t)(count)) : "memory")
#define CP_MBAR_ARRIVE(mbar) \
    asm volatile("cp.async.mbarrier.arrive.noinc.shared.b64 [%0];" :: "r"((uint32_t)(mbar)) : "memory")
#define MBAR_ARRIVE(mbar) \
    asm volatile("mbarrier.arrive.shared.b64 _, [%0];" :: "r"((uint32_t)(mbar)) : "memory")
#define MBARRIER_WAIT_PARITY(mbar, parity) do { \
    uint32_t _m = (uint32_t)(mbar); uint32_t _p = (uint32_t)(parity); uint32_t _d; \
    asm volatile("{\n\t.reg .pred p;\n\tmbarrier.try_wait.parity.acquire.cta.shared::cta.b64 p, [%1], %2;\n\tselp.b32 %0,1,0,p;\n\t}" \
                 : "=r"(_d) : "r"(_m), "r"(_p) : "memory"); \
    if (!_d) { \
        asm volatile("{\n\t.reg .pred P1;\n\tWL_%=:\n\tmbarrier.try_wait.parity.acquire.cta.shared::cta.b64 P1, [%0], %1, 0x989680;\n\t@P1 bra.uni WD_%=;\n\tbra.uni WL_%=;\n\tWD_%=:\n\t}" \
                     :: "r"(_m), "r"(_p) : "memory"); \
    } } while (0)

#define LDSM4(r, addr) \
    asm volatile("ldmatrix.sync.aligned.m8n8.x4.shared.b16 {%0,%1,%2,%3}, [%4];" \
                 : "=r"((r)[0]), "=r"((r)[1]), "=r"((r)[2]), "=r"((r)[3]) : "r"(addr))

#define MMA16816(d, a, b0, b1) \
    asm volatile("mma.sync.aligned.m16n8k16.row.col.f32.f16.f16.f32 " \
                 "{%0,%1,%2,%3}, {%4,%5,%6,%7}, {%8,%9}, {%0,%1,%2,%3};" \
                 : "+f"((d)[0]), "+f"((d)[1]), "+f"((d)[2]), "+f"((d)[3]) \
                 : "r"((a)[0]), "r"((a)[1]), "r"((a)[2]), "r"((a)[3]), "r"(b0), "r"(b1))

__device__ __forceinline__ float tanh_fast(float x) {
    float y;
    asm("tanh.approx.f32 %0, %1;" : "=f"(y) : "f"(x));
    return y;
}
__device__ __forceinline__ uint32_t cvt2(float x, float y) {
    __half2 h = __floats2half2_rn(x, y);
    return *(uint32_t*)&h;
}

// ---------------------------------------------------------------------------
// K0: fp32 -> fp16: keys (blocks [0,16384), MLP=4) and W2 (blocks [16384,17408))
// ---------------------------------------------------------------------------
__global__ __launch_bounds__(256) void convert_kernel(const float* __restrict__ keys,
                                                      const float* __restrict__ W2) {
    const int bx = blockIdx.x;
    if (bx < 16384) {
        const size_t base = (size_t)bx * 1024 + threadIdx.x;
        float4 f[4];
#pragma unroll
        for (int i = 0; i < 4; i++) f[i] = ((const float4*)keys)[base + i * 256];
#pragma unroll
        for (int i = 0; i < 4; i++)
            ((uint2*)g_keysh)[base + i * 256] =
                make_uint2(cvt2(f[i].x, f[i].y), cvt2(f[i].z, f[i].w));
    } else {
        int i4 = (bx - 16384) * 256 + threadIdx.x;
        float4 f = ((const float4*)W2)[i4];
        ((uint2*)g_w2h)[i4] = make_uint2(cvt2(f.x, f.y), cvt2(f.z, f.w));
    }
}

// ---------------------------------------------------------------------------
// K1: batch-tiled qproj — block computes 256 h-values x 8 batches.
// ---------------------------------------------------------------------------
__global__ __launch_bounds__(256) void qproj_kernel(const float* __restrict__ query,
                                                    const float* __restrict__ W1) {
    __shared__ float qs[8][KDIM];
    const int tid = threadIdx.x;
    const int b0 = blockIdx.y * 8;
    const int h = blockIdx.x * 256 + tid;
    for (int i = tid; i < 8 * KDIM / 4; i += 256) {
        int bb = i / (KDIM / 4), kk = (i % (KDIM / 4)) * 4;
        *(float4*)&qs[bb][kk] = *(const float4*)(query + (size_t)(b0 + bb) * KDIM + kk);
    }
    __syncthreads();
    const float* w = W1 + (size_t)h * KDIM;
    float acc[8];
#pragma unroll
    for (int bb = 0; bb < 8; bb++) acc[bb] = 0.f;
#pragma unroll 2
    for (int k = 0; k < KDIM; k += 4) {
        float4 w4 = *(const float4*)(w + k);
#pragma unroll
        for (int bb = 0; bb < 8; bb++) {
            acc[bb] = fmaf(qs[bb][k + 0], w4.x, acc[bb]);
            acc[bb] = fmaf(qs[bb][k + 1], w4.y, acc[bb]);
            acc[bb] = fmaf(qs[bb][k + 2], w4.z, acc[bb]);
            acc[bb] = fmaf(qs[bb][k + 3], w4.w, acc[bb]);
        }
    }
#pragma unroll
    for (int bb = 0; bb < 8; bb++)
        g_q[(b0 + bb) * HDIM + h] = acc[bb];
}

// ---------------------------------------------------------------------------
// K2: HMMA score kernel — 128x128 tile, 128 threads (4 warps, 2x2 grid,
// 64x64 per warp), 2 CTA/SM, 256 regs/thread budget.
// SMEM reads per chunk drop 96KB -> 64KB (A and B each read by 2 warps).
// mbarrier producer/consumer pipeline (3 stages).
// ---------------------------------------------------------------------------
#define BH_OFF   16384u
#define STAGE_SZ 32768u
#define MB_OFF   98304u
#define QS_OFF   98432u
#define VS_OFF   98944u
#define RED_OFF  99456u
#define SMEM_SCORE (99456 + 2048)

__device__ __forceinline__ void load_chunk(uint32_t st, int c, int R0, int h0,
                                           int lrow, int ltc) {
    const uint32_t swz = (uint32_t)((ltc ^ (lrow & 7)) << 4);
    const __half* gA = g_keysh + (size_t)R0 * KDIM + c * 64 + ltc * 8;
    const __half* gH = g_w2h + (size_t)h0 * KDIM + c * 64 + ltc * 8;
#pragma unroll
    for (int p = 0; p < 8; p++) {         // 128 threads: 16 rows per pass
        int r = lrow + (p << 4);
        uint32_t off = (uint32_t)(r << 7) + swz;
        size_t gi = (size_t)r * KDIM;
        cp_async16(st + off, gA + gi);
        cp_async16(st + BH_OFF + off, gH + gi);
    }
}

__global__ __launch_bounds__(128, 2) void score_kernel(const float* __restrict__ v) {
    extern __shared__ char smem[];
    const uint32_t sb = smem_to_u32(smem);
    const uint32_t mb = sb + MB_OFF;
    const int tid = threadIdx.x;
    const int lane = tid & 31, warp = tid >> 5;
    const int wm = warp & 1, wn = warp >> 1;      // 2 x 2 warp grid
    const int bx = blockIdx.x;
    const int nq = bx & 7, bm = bx >> 3;
    const int R0 = bm << 7, b = bm >> 3, h0 = nq << 7;

    float* qsp = (float*)(smem + QS_OFF);
    float* vsp = (float*)(smem + VS_OFF);
    float* red = (float*)(smem + RED_OFF);

    if (tid == 0) {
#pragma unroll
        for (int s = 0; s < 3; s++) {
            MBARRIER_INIT(mb + s * 16, 128);      // full[s]: per-thread cp.async arrive
            MBARRIER_INIT(mb + s * 16 + 8, 4);    // empty[s]: one arrive per warp
        }
    }
    qsp[tid] = g_q[b * HDIM + h0 + tid];
    vsp[tid] = v[h0 + tid];
    __syncthreads();

    float acc[4][8][4];                            // 64x64 per warp = 128 regs
#pragma unroll
    for (int i = 0; i < 4; i++)
#pragma unroll
        for (int j = 0; j < 8; j++)
#pragma unroll
            for (int e = 0; e < 4; e++) acc[i][j][e] = 0.f;

    const int lrow = tid >> 3, ltc = tid & 7;      // loader: 16 base rows x 8 granules
    const int rbank = lane & 7;
    const int a_sub = (((lane >> 3) & 1) << 3) + rbank;
    const int a_gl  = lane >> 4;
    const int b_sub = (((lane >> 4) & 1) << 3) + rbank;
    const int b_gl  = (lane >> 3) & 1;

    // prologue: fill stages 0,1 (chunks 0,1)
    load_chunk(sb, 0, R0, h0, lrow, ltc);
    CP_MBAR_ARRIVE(mb + 0);
    load_chunk(sb + STAGE_SZ, 1, R0, h0, lrow, ltc);
    CP_MBAR_ARRIVE(mb + 16);

#pragma unroll 1
    for (int c = 0; c < 16; c++) {
        const int c2 = c + 2;
        if (c2 < 16) {
            const int s2 = c2 % 3;
            if (c2 >= 3)
                MBARRIER_WAIT_PARITY(mb + s2 * 16 + 8, ((c2 / 3) - 1) & 1);
            load_chunk(sb + (uint32_t)s2 * STAGE_SZ, c2, R0, h0, lrow, ltc);
            CP_MBAR_ARRIVE(mb + s2 * 16);
        }
        const int s = c % 3;
        MBARRIER_WAIT_PARITY(mb + s * 16, (c / 3) & 1);
        const uint32_t stA = sb + (uint32_t)s * STAGE_SZ;

#pragma unroll
        for (int ks = 0; ks < 4; ks++) {
            uint32_t a[4][4], bh[4][4];
#pragma unroll
            for (int mi = 0; mi < 4; mi++) {
                int row = (wm << 6) + (mi << 4) + a_sub;
                int g = (ks << 1) + a_gl;
                LDSM4(a[mi], stA + (uint32_t)(row << 7) + (uint32_t)((g ^ rbank) << 4));
            }
#pragma unroll
            for (int nd = 0; nd < 4; nd++) {
                int row = (wn << 6) + (nd << 4) + b_sub;
                int g = (ks << 1) + b_gl;
                LDSM4(bh[nd], stA + BH_OFF + (uint32_t)(row << 7) + (uint32_t)((g ^ rbank) << 4));
            }
#pragma unroll
            for (int mi = 0; mi < 4; mi++)
#pragma unroll
                for (int ni = 0; ni < 8; ni++)
                    MMA16816(acc[mi][ni], a[mi], bh[ni >> 1][(ni & 1) * 2], bh[ni >> 1][(ni & 1) * 2 + 1]);
        }
        __syncwarp();
        if (lane == 0) MBAR_ARRIVE(mb + s * 16 + 8);   // warp done reading stage s
    }
    __syncthreads();

    // ---- fused epilogue: v-weighted tanh row sums ----
    const int rq = lane >> 2, j0 = (lane & 3) * 2;
    float rsum[4][2];
#pragma unroll
    for (int mi = 0; mi < 4; mi++) { rsum[mi][0] = 0.f; rsum[mi][1] = 0.f; }
#pragma unroll
    for (int mi = 0; mi < 4; mi++)
#pragma unroll
        for (int ni = 0; ni < 8; ni++) {
            int nb = (wn << 6) + (ni << 3) + j0;
            float q0 = qsp[nb], q1 = qsp[nb + 1];
            float v0 = vsp[nb], v1 = vsp[nb + 1];
            rsum[mi][0] = fmaf(v0, tanh_fast(q0 + acc[mi][ni][0]),
                          fmaf(v1, tanh_fast(q1 + acc[mi][ni][1]), rsum[mi][0]));
            rsum[mi][1] = fmaf(v0, tanh_fast(q0 + acc[mi][ni][2]),
                          fmaf(v1, tanh_fast(q1 + acc[mi][ni][3]), rsum[mi][1]));
        }
#pragma unroll
    for (int mi = 0; mi < 4; mi++)
#pragma unroll
        for (int h = 0; h < 2; h++) {
            float s = rsum[mi][h];
            s += __shfl_xor_sync(0xffffffffu, s, 1);
            s += __shfl_xor_sync(0xffffffffu, s, 2);
            if ((lane & 3) == 0)
                red[(wn << 7) + (wm << 6) + (mi << 4) + (h << 3) + rq] = s;
        }
    __syncthreads();
    {
        float s = red[tid] + red[128 + tid];
        g_spart[nq * (B_ * L_) + R0 + tid] = s;
    }
}

// ---------------------------------------------------------------------------
// K3: masked softmax (sums the 8 N-slab partials). mask is int32.
// ---------------------------------------------------------------------------
__global__ __launch_bounds__(256) void softmax_kernel(const int* __restrict__ mask,
                                                      float* __restrict__ wout) {
    const int b = blockIdx.x;
    const int tid = threadIdx.x;
    const float NINF = __int_as_float(0xff800000);
    __shared__ float sred[8];
    __shared__ float sbcast;

    float vals[4];
    float mx = NINF;
#pragma unroll
    for (int i = 0; i < 4; i++) {
        int idx = b * L_ + tid + i * 256;
        float s = 0.f;
#pragma unroll
        for (int p = 0; p < 8; p++) s += g_spart[p * (B_ * L_) + idx];
        if (mask[idx] != 0) s = NINF;
        vals[i] = s;
        mx = fmaxf(mx, s);
    }
#pragma unroll
    for (int off = 16; off > 0; off >>= 1)
        mx = fmaxf(mx, __shfl_xor_sync(0xffffffffu, mx, off));
    if ((tid & 31) == 0) sred[tid >> 5] = mx;
    __syncthreads();
    if (tid == 0) {
        float m = sred[0];
#pragma unroll
        for (int w = 1; w < 8; w++) m = fmaxf(m, sred[w]);
        sbcast = m;
    }
    __syncthreads();
    mx = sbcast;
    __syncthreads();

    float e[4];
    float sum = 0.f;
    if (mx == NINF) {
#pragma unroll
        for (int i = 0; i < 4; i++) e[i] = 0.f;
        sum = 1.f;
    } else {
#pragma unroll
        for (int i = 0; i < 4; i++) { e[i] = __expf(vals[i] - mx); sum += e[i]; }
    }
#pragma unroll
    for (int off = 16; off > 0; off >>= 1)
        sum += __shfl_xor_sync(0xffffffffu, sum, off);
    if ((tid & 31) == 0) sred[tid >> 5] = sum;
    __syncthreads();
    if (tid == 0) {
        float s = 0.f;
#pragma unroll
        for (int w = 0; w < 8; w++) s += sred[w];
        sbcast = (mx == NINF) ? 1.f : s;
    }
    __syncthreads();
    float inv = __fdividef(1.f, sbcast);
#pragma unroll
    for (int i = 0; i < 4; i++)
        wout[b * L_ + tid + i * 256] = e[i] * inv;
}

// ---------------------------------------------------------------------------
// K4a: context partials over 8 L-chunks of 128, reading fp16 keys
// ---------------------------------------------------------------------------
__global__ __launch_bounds__(256) void context_part_kernel(const float* __restrict__ wts) {
    const int b = blockIdx.y;
    const int chunk = blockIdx.z;
    const int col2 = blockIdx.x * 256 + threadIdx.x;
    __shared__ float ws[128];
    if (threadIdx.x < 128) ws[threadIdx.x] = wts[b * L_ + chunk * 128 + threadIdx.x];
    __syncthreads();
    const __half2* kp = (const __half2*)g_keysh + ((size_t)b * L_ + chunk * 128) * 512 + col2;
    float a0 = 0.f, a1 = 0.f;
#pragma unroll 8
    for (int l = 0; l < 128; l++) {
        float2 f = __half22float2(kp[(size_t)l * 512]);
        float w = ws[l];
        a0 = fmaf(w, f.x, a0);
        a1 = fmaf(w, f.y, a1);
    }
    float* dst = g_ctxpart + ((size_t)chunk * B_ + b) * KDIM + col2 * 2;
    *(float2*)dst = make_float2(a0, a1);
}

// ---------------------------------------------------------------------------
// K4b: sum the 8 context partials (deterministic)
// ---------------------------------------------------------------------------
__global__ __launch_bounds__(256) void context_reduce_kernel(float* __restrict__ ctx) {
    const int i = blockIdx.x * 256 + threadIdx.x;
    const int BK = B_ * KDIM;
    float s = 0.f;
#pragma unroll
    for (int p = 0; p < 8; p++) s += g_ctxpart[p * BK + i];
    ctx[i] = s;
}

// ---------------------------------------------------------------------------
extern "C" void kernel_launch(void* const* d_in, const int* in_sizes, int n_in,
                              void* d_out, int out_size) {
    const float* query = (const float*)d_in[0];   // [B, Q]
    const float* keys  = (const float*)d_in[1];   // [B, L, K]
    const int*   mask  = (const int*)d_in[2];     // [B, L] bool -> int32
    const float* W1    = (const float*)d_in[3];   // [H, Q]
    const float* W2    = (const float*)d_in[4];   // [H, K]
    const float* v     = (const float*)d_in[5];   // [1, H]

    float* out = (float*)d_out;
    float* ctx = out;                 // [B, K]
    float* wts = out + B_ * KDIM;     // [B, L]

    cudaFuncSetAttribute(score_kernel, cudaFuncAttributeMaxDynamicSharedMemorySize,
                         SMEM_SCORE);

    convert_kernel<<<17408, 256>>>(keys, W2);
    qproj_kernel<<<dim3(HDIM / 256, B_ / 8), 256>>>(query, W1);
    score_kernel<<<4096, 128, SMEM_SCORE>>>(v);
    softmax_kernel<<<B_, 256>>>(mask, wts);
    context_part_kernel<<<dim3(2, B_, 8), 256>>>(wts);
    context_reduce_kernel<<<B_ * KDIM / 256, 256>>>(ctx);
}